// round 9
// baseline (speedup 1.0000x reference)
#include <cuda_runtime.h>
#include <cuda_bf16.h>
#include <cstdint>

#define NUM_E 16
#define D_IN  2048
#define D_OUT 8192
#define T_TOK 8192

// GEMM: CTA 128x128, BK=32, 8 warps 2(M)x4(N), warp 64x32, 3-stage cp.async.
#define BM 128
#define BN 128
#define BK 32
#define NCHUNK (D_IN / BK)   // 64
#define THREADS 256
#define NSTAGE 3

// Per-stage smem: 4 tiles (Ah, Al, Bh, Bl), each 128 rows x 32 bf16 = 8KB,
// organized as 2 k16-halves of 4KB (128 rows x 32B, XOR swizzled).
#define REG_SZ  4096
#define A_HI    0
#define A_LO    8192
#define B_HI    16384
#define B_LO    24576
#define STAGE_B 32768
#define SMEM_BYTES (NSTAGE * STAGE_B)   // 98304

// Pre-split scratch (device global = sanctioned scratch; zero-init at load)
__device__ __nv_bfloat16 g_Ah[(size_t)T_TOK * D_IN];
__device__ __nv_bfloat16 g_Al[(size_t)T_TOK * D_IN];
__device__ __nv_bfloat16 g_Bh[(size_t)NUM_E * D_OUT * D_IN];
__device__ __nv_bfloat16 g_Bl[(size_t)NUM_E * D_OUT * D_IN];

__device__ __forceinline__ uint32_t swz(uint32_t a) {
    return a ^ ((a & 128u) >> 3);
}

__device__ __forceinline__ uint32_t smem_u32_of(const void* p) {
    uint32_t a;
    asm("{ .reg .u64 t; cvta.to.shared.u64 t, %1; cvt.u32.u64 %0, t; }" : "=r"(a) : "l"(p));
    return a;
}

__device__ __forceinline__ uint32_t pack2(__nv_bfloat16 a, __nv_bfloat16 b) {
    __nv_bfloat162 t = __halves2bfloat162(a, b);
    return *reinterpret_cast<uint32_t*>(&t);
}

__device__ __forceinline__ void cp16(uint32_t dst, const void* src) {
    asm volatile("cp.async.cg.shared.global [%0], [%1], 16;"
                 :: "r"(dst), "l"(src) : "memory");
}
__device__ __forceinline__ void cp_commit() {
    asm volatile("cp.async.commit_group;" ::: "memory");
}
__device__ __forceinline__ void cp_wait2() {
    asm volatile("cp.async.wait_group 2;" ::: "memory");
}

__device__ __forceinline__ void ldsm_x4(uint32_t* r, uint32_t addr) {
    asm volatile("ldmatrix.sync.aligned.m8n8.x4.shared.b16 {%0,%1,%2,%3}, [%4];"
                 : "=r"(r[0]), "=r"(r[1]), "=r"(r[2]), "=r"(r[3]) : "r"(addr));
}

__device__ __forceinline__ void mma_bf16(float* d, const uint32_t* a, uint32_t b0, uint32_t b1) {
    asm volatile(
        "mma.sync.aligned.m16n8k16.row.col.f32.bf16.bf16.f32 "
        "{%0,%1,%2,%3}, {%4,%5,%6,%7}, {%8,%9}, {%0,%1,%2,%3};"
        : "+f"(d[0]), "+f"(d[1]), "+f"(d[2]), "+f"(d[3])
        : "r"(a[0]), "r"(a[1]), "r"(a[2]), "r"(a[3]), "r"(b0), "r"(b1));
}

// ---- pre-pass: split fp32 -> bf16 hi/lo (4 elems per thread) ----
__global__ __launch_bounds__(256)
void convert_A_kernel(const float* __restrict__ src) {
    size_t i = (size_t)blockIdx.x * 256 + threadIdx.x;   // float4 index
    float4 v = reinterpret_cast<const float4*>(src)[i];
    __nv_bfloat16 h0 = __float2bfloat16(v.x), h1 = __float2bfloat16(v.y);
    __nv_bfloat16 h2 = __float2bfloat16(v.z), h3 = __float2bfloat16(v.w);
    uint2 hi = make_uint2(pack2(h0, h1), pack2(h2, h3));
    uint2 lo = make_uint2(
        pack2(__float2bfloat16(v.x - __bfloat162float(h0)),
              __float2bfloat16(v.y - __bfloat162float(h1))),
        pack2(__float2bfloat16(v.z - __bfloat162float(h2)),
              __float2bfloat16(v.w - __bfloat162float(h3))));
    reinterpret_cast<uint2*>(g_Ah)[i] = hi;
    reinterpret_cast<uint2*>(g_Al)[i] = lo;
}

__global__ __launch_bounds__(256)
void convert_B_kernel(const float* __restrict__ src) {
    size_t i = (size_t)blockIdx.x * 256 + threadIdx.x;
    float4 v = reinterpret_cast<const float4*>(src)[i];
    __nv_bfloat16 h0 = __float2bfloat16(v.x), h1 = __float2bfloat16(v.y);
    __nv_bfloat16 h2 = __float2bfloat16(v.z), h3 = __float2bfloat16(v.w);
    uint2 hi = make_uint2(pack2(h0, h1), pack2(h2, h3));
    uint2 lo = make_uint2(
        pack2(__float2bfloat16(v.x - __bfloat162float(h0)),
              __float2bfloat16(v.y - __bfloat162float(h1))),
        pack2(__float2bfloat16(v.z - __bfloat162float(h2)),
              __float2bfloat16(v.w - __bfloat162float(h3))));
    reinterpret_cast<uint2*>(g_Bh)[i] = hi;
    reinterpret_cast<uint2*>(g_Bl)[i] = lo;
}

// ---- main GEMM ----
__global__ __launch_bounds__(THREADS, 2)
void moe_gemm_cp_kernel(const float* __restrict__ bias,    // [E, D_OUT]
                        const int*   __restrict__ cnt,     // [E]
                        float*       __restrict__ out)     // [T, D_OUT]
{
    extern __shared__ char smem[];
    const uint32_t sbase = smem_u32_of(smem);

    const int tid = threadIdx.x;
    const int wid = tid >> 5;
    const int lid = tid & 31;

    const int nBase = blockIdx.x * BN;
    const int mBase = blockIdx.y * BM;

    int e = 0;
    {
        int acc = 0;
        #pragma unroll
        for (int i = 0; i < NUM_E; i++) {
            int c = cnt[i];
            if (mBase >= acc + c) { acc += c; e = i + 1; }
        }
    }

    const int warp_m = (wid >> 2) * 64;
    const int warp_n = (wid & 3) * 32;

    // ldmatrix lane addressing (verified rounds 3-8)
    const int a_row = (lid & 7) + ((lid >> 3) & 1) * 8;
    const int a_c2  = (lid >> 4) & 1;
    const int b_row = (lid & 7) + ((lid >> 4) & 1) * 8;
    const int b_c2  = (lid >> 3) & 1;

    // cp.async mapping: 512 x16B per 8KB tile, 2 ops/thread/tile.
    // idx = o*256 + tid -> row = idx>>2, p = idx&3 (16B piece of the row's 64B)
    // dst: h = p>>1 (k16 half), q = p&1 (16B within 32B row)
    const __nv_bfloat16* Ah = g_Ah;
    const __nv_bfloat16* Al = g_Al;
    const __nv_bfloat16* Bh = g_Bh + (size_t)e * D_OUT * D_IN;
    const __nv_bfloat16* Bl = g_Bl + (size_t)e * D_OUT * D_IN;

    uint32_t dsto[2];
    int rowo[2], po[2];
    #pragma unroll
    for (int o = 0; o < 2; o++) {
        int idx = o * 256 + tid;
        rowo[o] = idx >> 2;
        po[o]   = idx & 3;
        dsto[o] = (uint32_t)((po[o] >> 1) * REG_SZ) +
                  swz((uint32_t)(rowo[o] * 32 + (po[o] & 1) * 16));
    }

    float d[4][4][4];
    #pragma unroll
    for (int f = 0; f < 4; f++)
        #pragma unroll
        for (int n = 0; n < 4; n++)
            #pragma unroll
            for (int k = 0; k < 4; k++)
                d[f][n][k] = 0.0f;

    // issue one chunk's cp.asyncs into a stage
    auto issue = [&](int chunk, int stage) {
        const uint32_t st = sbase + (uint32_t)stage * STAGE_B;
        const int kb = chunk * BK;
        #pragma unroll
        for (int o = 0; o < 2; o++) {
            const size_t aoff = (size_t)(mBase + rowo[o]) * D_IN + kb + po[o] * 8;
            const size_t boff = (size_t)(nBase + rowo[o]) * D_IN + kb + po[o] * 8;
            cp16(st + A_HI + dsto[o], Ah + aoff);
            cp16(st + A_LO + dsto[o], Al + aoff);
            cp16(st + B_HI + dsto[o], Bh + boff);
            cp16(st + B_LO + dsto[o], Bl + boff);
        }
    };

    // prologue: chunks 0,1
    issue(0, 0); cp_commit();
    issue(1, 1); cp_commit();

    #pragma unroll 1
    for (int i = 0; i < NCHUNK; i++) {
        // keep 3 groups in flight; empty groups keep the count aligned
        if (i + 2 < NCHUNK) issue(i + 2, (i + 2) % NSTAGE);
        cp_commit();
        cp_wait2();
        __syncthreads();

        const uint32_t cur = sbase + (uint32_t)(i % NSTAGE) * STAGE_B;

        #pragma unroll
        for (int ks = 0; ks < 2; ks++) {
            const uint32_t hb = cur + (uint32_t)ks * REG_SZ;
            uint32_t bhf[2][4], blf[2][4];
            #pragma unroll
            for (int nb = 0; nb < 2; nb++) {
                uint32_t a = swz((uint32_t)((warp_n + nb * 16 + b_row) * 32 + b_c2 * 16));
                ldsm_x4(bhf[nb], hb + B_HI + a);
                ldsm_x4(blf[nb], hb + B_LO + a);
            }
            {
                uint32_t af[4][4];
                #pragma unroll
                for (int f = 0; f < 4; f++) {
                    uint32_t a = swz((uint32_t)((warp_m + f * 16 + a_row) * 32 + a_c2 * 16));
                    ldsm_x4(af[f], hb + A_HI + a);
                }
                #pragma unroll
                for (int f = 0; f < 4; f++)
                    #pragma unroll
                    for (int nb = 0; nb < 2; nb++) {
                        mma_bf16(d[f][nb * 2 + 0], af[f], bhf[nb][0], bhf[nb][1]);
                        mma_bf16(d[f][nb * 2 + 1], af[f], bhf[nb][2], bhf[nb][3]);
                    }
                #pragma unroll
                for (int f = 0; f < 4; f++)
                    #pragma unroll
                    for (int nb = 0; nb < 2; nb++) {
                        mma_bf16(d[f][nb * 2 + 0], af[f], blf[nb][0], blf[nb][1]);
                        mma_bf16(d[f][nb * 2 + 1], af[f], blf[nb][2], blf[nb][3]);
                    }
            }
            {
                uint32_t af[4][4];
                #pragma unroll
                for (int f = 0; f < 4; f++) {
                    uint32_t a = swz((uint32_t)((warp_m + f * 16 + a_row) * 32 + a_c2 * 16));
                    ldsm_x4(af[f], hb + A_LO + a);
                }
                #pragma unroll
                for (int f = 0; f < 4; f++)
                    #pragma unroll
                    for (int nb = 0; nb < 2; nb++) {
                        mma_bf16(d[f][nb * 2 + 0], af[f], bhf[nb][0], bhf[nb][1]);
                        mma_bf16(d[f][nb * 2 + 1], af[f], bhf[nb][2], bhf[nb][3]);
                    }
            }
        }
        __syncthreads();   // protect stage (i)%3 before iter i+1 issues into (i+3)%3
    }

    // ---- epilogue: bias + fp32 store ----
    const int g  = lid >> 2;
    const int t4 = lid & 3;
    const float* brow = bias + (size_t)e * D_OUT;
    #pragma unroll
    for (int f = 0; f < 4; f++) {
        const int row0 = mBase + warp_m + f * 16 + g;
        #pragma unroll
        for (int nf = 0; nf < 4; nf++) {
            const int col = nBase + warp_n + nf * 8 + t4 * 2;
            float2 bv = *reinterpret_cast<const float2*>(brow + col);
            float2 o0, o1;
            o0.x = d[f][nf][0] + bv.x;
            o0.y = d[f][nf][1] + bv.y;
            o1.x = d[f][nf][2] + bv.x;
            o1.y = d[f][nf][3] + bv.y;
            *reinterpret_cast<float2*>(out + (size_t)row0 * D_OUT + col) = o0;
            *reinterpret_cast<float2*>(out + (size_t)(row0 + 8) * D_OUT + col) = o1;
        }
    }
}

extern "C" void kernel_launch(void* const* d_in, const int* in_sizes, int n_in,
                              void* d_out, int out_size)
{
    const float* inp    = (const float*)d_in[0];
    const float* weight = (const float*)d_in[1];
    const float* bias   = (const float*)d_in[2];
    const int*   cnt    = (const int*)d_in[3];
    float* out = (float*)d_out;

    // pre-pass: split fp32 -> bf16 hi/lo scratch
    {
        size_t a4 = (size_t)T_TOK * D_IN / 4;              // 4,194,304
        size_t b4 = (size_t)NUM_E * D_OUT * D_IN / 4;      // 67,108,864
        convert_A_kernel<<<(unsigned)(a4 / 256), 256>>>(inp);
        convert_B_kernel<<<(unsigned)(b4 / 256), 256>>>(weight);
    }

    cudaFuncSetAttribute(moe_gemm_cp_kernel,
                         cudaFuncAttributeMaxDynamicSharedMemorySize, SMEM_BYTES);
    dim3 grid(D_OUT / BN, T_TOK / BM);   // (64, 64)
    moe_gemm_cp_kernel<<<grid, THREADS, SMEM_BYTES>>>(bias, cnt, out);
}

// round 10
// speedup vs baseline: 1.1739x; 1.1739x over previous
#include <cuda_runtime.h>
#include <cuda_fp16.h>
#include <cstdint>

#define NUM_E 16
#define D_IN  2048
#define D_OUT 8192
#define T_TOK 8192

// CTA 128(M) x 128(N), BK=32. 8 warps = 2(M) x 4(N), warp tile 64x32.
// fp16 2-term: A single fp16 (rn), B split hi+lo. Double-buffered, 2 CTAs/SM.
#define BM 128
#define BN 128
#define BK 32
#define NCHUNK (D_IN / BK)   // 64
#define THREADS 256

// Packed smem: per k16-half region = 128 rows x 32B (4KB), XOR-swizzled.
// Tiles: A (8KB), B_HI (8KB), B_LO (8KB). Stage 24KB, 2 stages = 48KB.
#define REG_SZ  4096
#define A_T     0
#define B_HI    8192
#define B_LO    16384
#define STAGE_B 24576
#define SMEM_BYTES (2 * STAGE_B)   // 49152

__device__ __forceinline__ uint32_t swz(uint32_t a) {
    return a ^ ((a & 128u) >> 3);
}

__device__ __forceinline__ uint32_t smem_u32_of(const void* p) {
    uint32_t a;
    asm("{ .reg .u64 t; cvta.to.shared.u64 t, %1; cvt.u32.u64 %0, t; }" : "=r"(a) : "l"(p));
    return a;
}

__device__ __forceinline__ uint32_t pack2h(__half a, __half b) {
    __half2 t = __halves2half2(a, b);
    return *reinterpret_cast<uint32_t*>(&t);
}

__device__ __forceinline__ void sts8(uint32_t addr, uint32_t x, uint32_t y) {
    asm volatile("st.shared.v2.b32 [%0], {%1, %2};" :: "r"(addr), "r"(x), "r"(y) : "memory");
}

// A: store rn-rounded fp16 only (8B per float4).
__device__ __forceinline__ void store_a4(float4 v, uint32_t addr) {
    sts8(addr,
         pack2h(__float2half_rn(v.x), __float2half_rn(v.y)),
         pack2h(__float2half_rn(v.z), __float2half_rn(v.w)));
}

// B: split into fp16 hi + residual lo (8B each).
__device__ __forceinline__ void split_store_b4(float4 v, uint32_t hi_addr, uint32_t lo_addr) {
    __half h0 = __float2half_rn(v.x);
    __half h1 = __float2half_rn(v.y);
    __half h2 = __float2half_rn(v.z);
    __half h3 = __float2half_rn(v.w);
    __half l0 = __float2half_rn(v.x - __half2float(h0));
    __half l1 = __float2half_rn(v.y - __half2float(h1));
    __half l2 = __float2half_rn(v.z - __half2float(h2));
    __half l3 = __float2half_rn(v.w - __half2float(h3));
    sts8(hi_addr, pack2h(h0, h1), pack2h(h2, h3));
    sts8(lo_addr, pack2h(l0, l1), pack2h(l2, l3));
}

__device__ __forceinline__ void ldsm_x4(uint32_t* r, uint32_t addr) {
    asm volatile("ldmatrix.sync.aligned.m8n8.x4.shared.b16 {%0,%1,%2,%3}, [%4];"
                 : "=r"(r[0]), "=r"(r[1]), "=r"(r[2]), "=r"(r[3]) : "r"(addr));
}

__device__ __forceinline__ void mma_f16(float* d, const uint32_t* a, uint32_t b0, uint32_t b1) {
    asm volatile(
        "mma.sync.aligned.m16n8k16.row.col.f32.f16.f16.f32 "
        "{%0,%1,%2,%3}, {%4,%5,%6,%7}, {%8,%9}, {%0,%1,%2,%3};"
        : "+f"(d[0]), "+f"(d[1]), "+f"(d[2]), "+f"(d[3])
        : "r"(a[0]), "r"(a[1]), "r"(a[2]), "r"(a[3]), "r"(b0), "r"(b1));
}

__global__ __launch_bounds__(THREADS, 2)
void moe_gemm_f16_kernel(const float* __restrict__ inp,     // [T, D_IN]
                         const float* __restrict__ weight,  // [E, D_OUT, D_IN]
                         const float* __restrict__ bias,    // [E, D_OUT]
                         const int*   __restrict__ cnt,     // [E]
                         float*       __restrict__ out)     // [T, D_OUT]
{
    extern __shared__ char smem[];
    const uint32_t sbase = smem_u32_of(smem);

    const int tid = threadIdx.x;
    const int wid = tid >> 5;
    const int lid = tid & 31;

    const int nBase = blockIdx.x * BN;
    const int mBase = blockIdx.y * BM;

    int e = 0;
    {
        int acc = 0;
        #pragma unroll
        for (int i = 0; i < NUM_E; i++) {
            int c = cnt[i];
            if (mBase >= acc + c) { acc += c; e = i + 1; }
        }
    }
    const float* wptr = weight + (size_t)e * D_OUT * D_IN;

    const int warp_m = (wid >> 2) * 64;
    const int warp_n = (wid & 3) * 32;

    // ldmatrix lane addressing (verified rounds 3-9)
    const int a_row = (lid & 7) + ((lid >> 3) & 1) * 8;
    const int a_c2  = (lid >> 4) & 1;
    const int b_row = (lid & 7) + ((lid >> 4) & 1) * 8;
    const int b_c2  = (lid >> 3) & 1;

    // Coalesced staging (round-7 mapping): warp inst covers 4 rows x 128B.
    const int srow = wid * 4 + (lid >> 3);     // 0..31, +r*32
    const int quad = lid & 7;
    const uint32_t piece = swz((uint32_t)(srow * 32 + (quad & 3) * 8));
    const uint32_t half_off = (uint32_t)((quad >> 2) * REG_SZ);

    const float* aG = inp  + (size_t)(mBase + srow) * D_IN + quad * 4;
    const float* bG = wptr + (size_t)(nBase + srow) * D_IN + quad * 4;

    float d[4][4][4];
    #pragma unroll
    for (int f = 0; f < 4; f++)
        #pragma unroll
        for (int n = 0; n < 4; n++)
            #pragma unroll
            for (int k = 0; k < 4; k++)
                d[f][n][k] = 0.0f;

    // ---- prologue: chunk 0 into stage 0 ----
    {
        float4 aS[4], bS[4];
        #pragma unroll
        for (int r = 0; r < 4; r++) {
            aS[r] = *reinterpret_cast<const float4*>(aG + (size_t)(r * 32) * D_IN);
            bS[r] = *reinterpret_cast<const float4*>(bG + (size_t)(r * 32) * D_IN);
        }
        #pragma unroll
        for (int r = 0; r < 4; r++) {
            uint32_t off = half_off + piece + (uint32_t)(r * 1024);
            store_a4(aS[r], sbase + A_T + off);
            split_store_b4(bS[r], sbase + B_HI + off, sbase + B_LO + off);
        }
    }
    __syncthreads();

    #pragma unroll 1
    for (int i = 0; i < NCHUNK; i++) {
        const uint32_t cur = sbase + (uint32_t)(i & 1) * STAGE_B;
        const uint32_t nxt = sbase + (uint32_t)((i + 1) & 1) * STAGE_B;
        const bool pf = (i + 1 < NCHUNK);
        const int kb = (i + 1) * BK;

        float4 aS[4];
        if (pf) {
            #pragma unroll
            for (int r = 0; r < 4; r++)
                aS[r] = *reinterpret_cast<const float4*>(aG + kb + (size_t)(r * 32) * D_IN);
        }

        // ---- k16 step 0 ----
        {
            const uint32_t hb = cur;
            uint32_t bh[2][4], bl[2][4];
            #pragma unroll
            for (int nb = 0; nb < 2; nb++) {
                uint32_t a = swz((uint32_t)((warp_n + nb * 16 + b_row) * 32 + b_c2 * 16));
                ldsm_x4(bh[nb], hb + B_HI + a);
                ldsm_x4(bl[nb], hb + B_LO + a);
            }
            uint32_t af[4][4];
            #pragma unroll
            for (int f = 0; f < 4; f++) {
                uint32_t a = swz((uint32_t)((warp_m + f * 16 + a_row) * 32 + a_c2 * 16));
                ldsm_x4(af[f], hb + A_T + a);
            }
            #pragma unroll
            for (int f = 0; f < 4; f++)
                #pragma unroll
                for (int nb = 0; nb < 2; nb++) {
                    mma_f16(d[f][nb * 2 + 0], af[f], bh[nb][0], bh[nb][1]);
                    mma_f16(d[f][nb * 2 + 1], af[f], bh[nb][2], bh[nb][3]);
                }
            #pragma unroll
            for (int f = 0; f < 4; f++)
                #pragma unroll
                for (int nb = 0; nb < 2; nb++) {
                    mma_f16(d[f][nb * 2 + 0], af[f], bl[nb][0], bl[nb][1]);
                    mma_f16(d[f][nb * 2 + 1], af[f], bl[nb][2], bl[nb][3]);
                }
        }

        // store prefetched A, then load next B
        float4 bS[4];
        if (pf) {
            #pragma unroll
            for (int r = 0; r < 4; r++) {
                uint32_t off = half_off + piece + (uint32_t)(r * 1024);
                store_a4(aS[r], nxt + A_T + off);
            }
            #pragma unroll
            for (int r = 0; r < 4; r++)
                bS[r] = *reinterpret_cast<const float4*>(bG + kb + (size_t)(r * 32) * D_IN);
        }

        // ---- k16 step 1 ----
        {
            const uint32_t hb = cur + REG_SZ;
            uint32_t bh[2][4], bl[2][4];
            #pragma unroll
            for (int nb = 0; nb < 2; nb++) {
                uint32_t a = swz((uint32_t)((warp_n + nb * 16 + b_row) * 32 + b_c2 * 16));
                ldsm_x4(bh[nb], hb + B_HI + a);
                ldsm_x4(bl[nb], hb + B_LO + a);
            }
            uint32_t af[4][4];
            #pragma unroll
            for (int f = 0; f < 4; f++) {
                uint32_t a = swz((uint32_t)((warp_m + f * 16 + a_row) * 32 + a_c2 * 16));
                ldsm_x4(af[f], hb + A_T + a);
            }
            #pragma unroll
            for (int f = 0; f < 4; f++)
                #pragma unroll
                for (int nb = 0; nb < 2; nb++) {
                    mma_f16(d[f][nb * 2 + 0], af[f], bh[nb][0], bh[nb][1]);
                    mma_f16(d[f][nb * 2 + 1], af[f], bh[nb][2], bh[nb][3]);
                }
            #pragma unroll
            for (int f = 0; f < 4; f++)
                #pragma unroll
                for (int nb = 0; nb < 2; nb++) {
                    mma_f16(d[f][nb * 2 + 0], af[f], bl[nb][0], bl[nb][1]);
                    mma_f16(d[f][nb * 2 + 1], af[f], bl[nb][2], bl[nb][3]);
                }
        }

        if (pf) {
            #pragma unroll
            for (int r = 0; r < 4; r++) {
                uint32_t off = half_off + piece + (uint32_t)(r * 1024);
                split_store_b4(bS[r], nxt + B_HI + off, nxt + B_LO + off);
            }
        }
        __syncthreads();
    }

    // ---- epilogue: bias + fp32 store ----
    const int g  = lid >> 2;
    const int t4 = lid & 3;
    const float* brow = bias + (size_t)e * D_OUT;
    #pragma unroll
    for (int f = 0; f < 4; f++) {
        const int row0 = mBase + warp_m + f * 16 + g;
        #pragma unroll
        for (int nf = 0; nf < 4; nf++) {
            const int col = nBase + warp_n + nf * 8 + t4 * 2;
            float2 bv = *reinterpret_cast<const float2*>(brow + col);
            float2 o0, o1;
            o0.x = d[f][nf][0] + bv.x;
            o0.y = d[f][nf][1] + bv.y;
            o1.x = d[f][nf][2] + bv.x;
            o1.y = d[f][nf][3] + bv.y;
            *reinterpret_cast<float2*>(out + (size_t)row0 * D_OUT + col) = o0;
            *reinterpret_cast<float2*>(out + (size_t)(row0 + 8) * D_OUT + col) = o1;
        }
    }
}

extern "C" void kernel_launch(void* const* d_in, const int* in_sizes, int n_in,
                              void* d_out, int out_size)
{
    const float* inp    = (const float*)d_in[0];
    const float* weight = (const float*)d_in[1];
    const float* bias   = (const float*)d_in[2];
    const int*   cnt    = (const int*)d_in[3];
    float* out = (float*)d_out;

    cudaFuncSetAttribute(moe_gemm_f16_kernel,
                         cudaFuncAttributeMaxDynamicSharedMemorySize, SMEM_BYTES);

    dim3 grid(D_OUT / BN, T_TOK / BM);   // (64, 64)
    moe_gemm_f16_kernel<<<grid, THREADS, SMEM_BYTES>>>(inp, weight, bias, cnt, out);
}

// round 11
// speedup vs baseline: 1.9346x; 1.6480x over previous
#include <cuda_runtime.h>
#include <cuda_fp16.h>
#include <cstdint>

#define NUM_E 16
#define D_IN  2048
#define D_OUT 8192
#define T_TOK 8192

// CTA 128(M) x 128(N), BK=64 (4 k16 steps/chunk, 1 sync/chunk).
// 8 warps = 2(M) x 4(N), warp tile 64x32. fp16 2-term (A rn, B hi+lo).
#define BM 128
#define BN 128
#define BK 64
#define NCHUNK (D_IN / BK)   // 32
#define THREADS 256

// smem: per k16-half region = 128 rows x 32B (4KB), XOR-swizzled. 4 halves per tile.
#define REG_SZ  4096
#define A_T     0                     // 16KB (4 halves)
#define B_HI    16384                 // 16KB
#define B_LO    32768                 // 16KB
#define STAGE_B 49152
#define SMEM_BYTES (2 * STAGE_B)      // 98304

__device__ __forceinline__ uint32_t swz(uint32_t a) {
    return a ^ ((a & 128u) >> 3);
}

__device__ __forceinline__ uint32_t smem_u32_of(const void* p) {
    uint32_t a;
    asm("{ .reg .u64 t; cvta.to.shared.u64 t, %1; cvt.u32.u64 %0, t; }" : "=r"(a) : "l"(p));
    return a;
}

__device__ __forceinline__ uint32_t pack2h(__half a, __half b) {
    __half2 t = __halves2half2(a, b);
    return *reinterpret_cast<uint32_t*>(&t);
}

__device__ __forceinline__ void sts8(uint32_t addr, uint32_t x, uint32_t y) {
    asm volatile("st.shared.v2.b32 [%0], {%1, %2};" :: "r"(addr), "r"(x), "r"(y) : "memory");
}

__device__ __forceinline__ void store_a4(float4 v, uint32_t addr) {
    sts8(addr,
         pack2h(__float2half_rn(v.x), __float2half_rn(v.y)),
         pack2h(__float2half_rn(v.z), __float2half_rn(v.w)));
}

__device__ __forceinline__ void split_store_b4(float4 v, uint32_t hi_addr, uint32_t lo_addr) {
    __half h0 = __float2half_rn(v.x);
    __half h1 = __float2half_rn(v.y);
    __half h2 = __float2half_rn(v.z);
    __half h3 = __float2half_rn(v.w);
    __half l0 = __float2half_rn(v.x - __half2float(h0));
    __half l1 = __float2half_rn(v.y - __half2float(h1));
    __half l2 = __float2half_rn(v.z - __half2float(h2));
    __half l3 = __float2half_rn(v.w - __half2float(h3));
    sts8(hi_addr, pack2h(h0, h1), pack2h(h2, h3));
    sts8(lo_addr, pack2h(l0, l1), pack2h(l2, l3));
}

__device__ __forceinline__ void ldsm_x4(uint32_t* r, uint32_t addr) {
    asm volatile("ldmatrix.sync.aligned.m8n8.x4.shared.b16 {%0,%1,%2,%3}, [%4];"
                 : "=r"(r[0]), "=r"(r[1]), "=r"(r[2]), "=r"(r[3]) : "r"(addr));
}

__device__ __forceinline__ void mma_f16(float* d, const uint32_t* a, uint32_t b0, uint32_t b1) {
    asm volatile(
        "mma.sync.aligned.m16n8k16.row.col.f32.f16.f16.f32 "
        "{%0,%1,%2,%3}, {%4,%5,%6,%7}, {%8,%9}, {%0,%1,%2,%3};"
        : "+f"(d[0]), "+f"(d[1]), "+f"(d[2]), "+f"(d[3])
        : "r"(a[0]), "r"(a[1]), "r"(a[2]), "r"(a[3]), "r"(b0), "r"(b1));
}

__global__ __launch_bounds__(THREADS, 2)
void moe_gemm_f16b_kernel(const float* __restrict__ inp,     // [T, D_IN]
                          const float* __restrict__ weight,  // [E, D_OUT, D_IN]
                          const float* __restrict__ bias,    // [E, D_OUT]
                          const int*   __restrict__ cnt,     // [E]
                          float*       __restrict__ out)     // [T, D_OUT]
{
    extern __shared__ char smem[];
    const uint32_t sbase = smem_u32_of(smem);

    const int tid = threadIdx.x;
    const int wid = tid >> 5;
    const int lid = tid & 31;

    const int nBase = blockIdx.x * BN;
    const int mBase = blockIdx.y * BM;

    int e = 0;
    {
        int acc = 0;
        #pragma unroll
        for (int i = 0; i < NUM_E; i++) {
            int c = cnt[i];
            if (mBase >= acc + c) { acc += c; e = i + 1; }
        }
    }
    const float* wptr = weight + (size_t)e * D_OUT * D_IN;

    const int warp_m = (wid >> 2) * 64;
    const int warp_n = (wid & 3) * 32;

    // ldmatrix lane addressing (verified rounds 3-10)
    const int a_row = (lid & 7) + ((lid >> 3) & 1) * 8;
    const int a_c2  = (lid >> 4) & 1;
    const int b_row = (lid & 7) + ((lid >> 4) & 1) * 8;
    const int b_c2  = (lid >> 3) & 1;

    // Staging mapping: warp inst covers 4 rows x 128B. Per sub-load (32 cols):
    // rows srow + r*32 (r=0..3), col quad q = lid&7 -> cols q*4 within the 32.
    // smem dest: half = (q>>2) + sub*2, piece = swz(row*32 + (q&3)*8).
    const int srow = wid * 4 + (lid >> 3);
    const int quad = lid & 7;
    const uint32_t piece = swz((uint32_t)(srow * 32 + (quad & 3) * 8));
    const uint32_t h_lo = (uint32_t)((quad >> 2) * REG_SZ);         // sub 0
    const uint32_t h_hi = h_lo + 2 * REG_SZ;                        // sub 1

    const float* aG = inp  + (size_t)(mBase + srow) * D_IN + quad * 4;
    const float* bG = wptr + (size_t)(nBase + srow) * D_IN + quad * 4;

    float d[4][4][4];
    #pragma unroll
    for (int f = 0; f < 4; f++)
        #pragma unroll
        for (int n = 0; n < 4; n++)
            #pragma unroll
            for (int k = 0; k < 4; k++)
                d[f][n][k] = 0.0f;

    // one k16 compute step
    auto k16 = [&](uint32_t hb) {
        uint32_t bh[2][4], bl[2][4];
        #pragma unroll
        for (int nb = 0; nb < 2; nb++) {
            uint32_t a = swz((uint32_t)((warp_n + nb * 16 + b_row) * 32 + b_c2 * 16));
            ldsm_x4(bh[nb], hb + B_HI + a);
            ldsm_x4(bl[nb], hb + B_LO + a);
        }
        uint32_t af[4][4];
        #pragma unroll
        for (int f = 0; f < 4; f++) {
            uint32_t a = swz((uint32_t)((warp_m + f * 16 + a_row) * 32 + a_c2 * 16));
            ldsm_x4(af[f], hb + A_T + a);
        }
        #pragma unroll
        for (int f = 0; f < 4; f++)
            #pragma unroll
            for (int nb = 0; nb < 2; nb++) {
                mma_f16(d[f][nb * 2 + 0], af[f], bh[nb][0], bh[nb][1]);
                mma_f16(d[f][nb * 2 + 1], af[f], bh[nb][2], bh[nb][3]);
            }
        #pragma unroll
        for (int f = 0; f < 4; f++)
            #pragma unroll
            for (int nb = 0; nb < 2; nb++) {
                mma_f16(d[f][nb * 2 + 0], af[f], bl[nb][0], bl[nb][1]);
                mma_f16(d[f][nb * 2 + 1], af[f], bl[nb][2], bl[nb][3]);
            }
    };

    // fill a full chunk (both A subs, both B subs) -- used for prologue
    auto fill_full = [&](int chunk, uint32_t st) {
        const int kb = chunk * BK;
        #pragma unroll
        for (int sub = 0; sub < 2; sub++) {
            float4 s[4];
            #pragma unroll
            for (int r = 0; r < 4; r++)
                s[r] = *reinterpret_cast<const float4*>(aG + kb + sub * 32 + (size_t)(r * 32) * D_IN);
            const uint32_t ho = (sub ? h_hi : h_lo);
            #pragma unroll
            for (int r = 0; r < 4; r++)
                store_a4(s[r], st + A_T + ho + piece + (uint32_t)(r * 1024));
        }
        #pragma unroll
        for (int sub = 0; sub < 2; sub++) {
            float4 s[4];
            #pragma unroll
            for (int r = 0; r < 4; r++)
                s[r] = *reinterpret_cast<const float4*>(bG + kb + sub * 32 + (size_t)(r * 32) * D_IN);
            const uint32_t ho = (sub ? h_hi : h_lo);
            #pragma unroll
            for (int r = 0; r < 4; r++)
                split_store_b4(s[r], st + B_HI + ho + piece + (uint32_t)(r * 1024),
                                     st + B_LO + ho + piece + (uint32_t)(r * 1024));
        }
    };

    fill_full(0, sbase);
    __syncthreads();

    float4 s[4];   // staging registers, reused across the 4 transfer slots

    #pragma unroll 1
    for (int i = 0; i < NCHUNK; i++) {
        const uint32_t cur = sbase + (uint32_t)(i & 1) * STAGE_B;
        const uint32_t nxt = sbase + (uint32_t)((i + 1) & 1) * STAGE_B;
        const bool pf = (i + 1 < NCHUNK);
        const int kb = (i + 1) * BK;

        // slot 0: LDG A sub0
        if (pf) {
            #pragma unroll
            for (int r = 0; r < 4; r++)
                s[r] = *reinterpret_cast<const float4*>(aG + kb + (size_t)(r * 32) * D_IN);
        }
        k16(cur);

        // slot 1: STS A sub0, LDG A sub1
        if (pf) {
            #pragma unroll
            for (int r = 0; r < 4; r++)
                store_a4(s[r], nxt + A_T + h_lo + piece + (uint32_t)(r * 1024));
            #pragma unroll
            for (int r = 0; r < 4; r++)
                s[r] = *reinterpret_cast<const float4*>(aG + kb + 32 + (size_t)(r * 32) * D_IN);
        }
        k16(cur + REG_SZ);

        // slot 2: STS A sub1, LDG B sub0
        if (pf) {
            #pragma unroll
            for (int r = 0; r < 4; r++)
                store_a4(s[r], nxt + A_T + h_hi + piece + (uint32_t)(r * 1024));
            #pragma unroll
            for (int r = 0; r < 4; r++)
                s[r] = *reinterpret_cast<const float4*>(bG + kb + (size_t)(r * 32) * D_IN);
        }
        k16(cur + 2 * REG_SZ);

        // slot 3: STS B sub0, LDG B sub1
        if (pf) {
            #pragma unroll
            for (int r = 0; r < 4; r++)
                split_store_b4(s[r], nxt + B_HI + h_lo + piece + (uint32_t)(r * 1024),
                                     nxt + B_LO + h_lo + piece + (uint32_t)(r * 1024));
            #pragma unroll
            for (int r = 0; r < 4; r++)
                s[r] = *reinterpret_cast<const float4*>(bG + kb + 32 + (size_t)(r * 32) * D_IN);
        }
        k16(cur + 3 * REG_SZ);

        // slot 4: STS B sub1
        if (pf) {
            #pragma unroll
            for (int r = 0; r < 4; r++)
                split_store_b4(s[r], nxt + B_HI + h_hi + piece + (uint32_t)(r * 1024),
                                     nxt + B_LO + h_hi + piece + (uint32_t)(r * 1024));
        }
        __syncthreads();
    }

    // ---- epilogue: bias + fp32 store ----
    const int g  = lid >> 2;
    const int t4 = lid & 3;
    const float* brow = bias + (size_t)e * D_OUT;
    #pragma unroll
    for (int f = 0; f < 4; f++) {
        const int row0 = mBase + warp_m + f * 16 + g;
        #pragma unroll
        for (int nf = 0; nf < 4; nf++) {
            const int col = nBase + warp_n + nf * 8 + t4 * 2;
            float2 bv = *reinterpret_cast<const float2*>(brow + col);
            float2 o0, o1;
            o0.x = d[f][nf][0] + bv.x;
            o0.y = d[f][nf][1] + bv.y;
            o1.x = d[f][nf][2] + bv.x;
            o1.y = d[f][nf][3] + bv.y;
            *reinterpret_cast<float2*>(out + (size_t)row0 * D_OUT + col) = o0;
            *reinterpret_cast<float2*>(out + (size_t)(row0 + 8) * D_OUT + col) = o1;
        }
    }
}

extern "C" void kernel_launch(void* const* d_in, const int* in_sizes, int n_in,
                              void* d_out, int out_size)
{
    const float* inp    = (const float*)d_in[0];
    const float* weight = (const float*)d_in[1];
    const float* bias   = (const float*)d_in[2];
    const int*   cnt    = (const int*)d_in[3];
    float* out = (float*)d_out;

    cudaFuncSetAttribute(moe_gemm_f16b_kernel,
                         cudaFuncAttributeMaxDynamicSharedMemorySize, SMEM_BYTES);

    dim3 grid(D_OUT / BN, T_TOK / BM);   // (64, 64)
    moe_gemm_f16b_kernel<<<grid, THREADS, SMEM_BYTES>>>(inp, weight, bias, cnt, out);
}